// round 14
// baseline (speedup 1.0000x reference)
#include <cuda_runtime.h>
#include <cstdint>

typedef unsigned long long u64;

#define BATCH 8
#define DIM   64
#define TLEN  16384
#define INNER 128
#define TT    128
#define NTILES (TLEN/TT)
#define TTO   256
#define NTILES_O (TLEN/TTO)
#define LOG2E 1.4426950408889634f

// Scratch (device globals; no runtime allocation)
__device__ float g_E[(size_t)BATCH*INNER*TLEN];   // 64 MB: exp(qraw)
__device__ float g_qsum[BATCH*INNER];
__device__ float g_ksum[BATCH*INNER];
__device__ float g_xsum[BATCH*DIM];
__device__ float g_At[BATCH*INNER*64];            // A transposed: [b][c][o]
__device__ float g_W2[2*DIM*INNER];               // [w][kk][c]: transposed, *log2e

// ---- packed fp32x2 helpers (Blackwell) ----
__device__ __forceinline__ u64 pack2(float lo, float hi) {
    u64 r; asm("mov.b64 %0, {%1,%2};" : "=l"(r) : "f"(lo), "f"(hi)); return r;
}
__device__ __forceinline__ float2 unpack2(u64 v) {
    float lo, hi; asm("mov.b64 {%0,%1}, %2;" : "=f"(lo), "=f"(hi) : "l"(v));
    return make_float2(lo, hi);
}
__device__ __forceinline__ void fma2(u64 &d, u64 a, u64 b) {
    asm("fma.rn.f32x2 %0, %1, %2, %0;" : "+l"(d) : "l"(a), "l"(b));
}
__device__ __forceinline__ u64 add2(u64 a, u64 b) {
    u64 r; asm("add.rn.f32x2 %0, %1, %2;" : "=l"(r) : "l"(a), "l"(b)); return r;
}
__device__ __forceinline__ float ex2(float x) {
    float r; asm("ex2.approx.f32 %0, %1;" : "=f"(r) : "f"(x)); return r;
}
__device__ __forceinline__ float rcpa(float x) {
    float r; asm("rcp.approx.f32 %0, %1;" : "=f"(r) : "f"(x)); return r;
}
__device__ __forceinline__ uint32_t smem_u32(const void* p) {
    uint32_t a;
    asm("{ .reg .u64 t; cvta.to.shared.u64 t, %1; cvt.u32.u64 %0, t; }"
        : "=r"(a) : "l"(p));
    return a;
}
__device__ __forceinline__ void cp16(uint32_t dst, const void* src) {
    asm volatile("cp.async.cg.shared.global [%0], [%1], 16;" :: "r"(dst), "l"(src));
}
#define CP_COMMIT() asm volatile("cp.async.commit_group;" ::: "memory")
#define CP_WAIT(N)  asm volatile("cp.async.wait_group %0;" :: "n"(N) : "memory")

// Merged setup: zero accumulators + pre-transform W (transpose + *log2e).
__global__ void k_setup(const float* __restrict__ wqkv) {
    int i = blockIdx.x*blockDim.x + threadIdx.x;
    if (i < BATCH*INNER) { g_qsum[i] = 0.f; g_ksum[i] = 0.f; }
    if (i < BATCH*DIM)   { g_xsum[i] = 0.f; }
    for (int idx = i; idx < 2*DIM*INNER; idx += gridDim.x*blockDim.x) {
        int w = idx >> 13;
        int r = idx & 8191;
        int kk = r >> 7, c = r & 127;
        g_W2[idx] = wqkv[w*INNER*DIM + c*DIM + kk] * LOG2E;
    }
}

// Pass 1 (FUSED): one kk-loop computes qraw AND kraw accumulators, reading
// the x tile once. acc*: [j][p], j = channel ty*8+j, p = t-pairs of quads
// {tx*4..+3} and {64+tx*4..+3} (conflict-free LDS.128).
__global__ void __launch_bounds__(256) k_reduce(const float* __restrict__ x) {
    extern __shared__ float sm[];
    float* wsq = sm;                 // [64][128] 32 KB
    float* wsk = sm + DIM*INNER;     // [64][128] 32 KB
    float* xs  = sm + 2*DIM*INNER;   // [64][TT]  32 KB
    float* red = xs + DIM*TT;        // [16][TT]   8 KB
    const int b   = blockIdx.y;
    const int t0  = blockIdx.x * TT;
    const int tid = threadIdx.x;
    const int tx  = tid & 15;   // t quads at tx*4 and 64+tx*4
    const int ty  = tid >> 4;   // c subtile (8 consecutive c each)

    // ---- async fills: wsq, wsk (straight copies), xs (row-chunked) ----
    {
        const uint32_t s_wsq = smem_u32(wsq) + tid*16;
        const uint32_t s_wsk = smem_u32(wsk) + tid*16;
        const uint32_t s_xs  = smem_u32(xs)  + tid*16;
        const char* wq = (const char*)g_W2 + tid*16;
        const char* wk = (const char*)(g_W2 + DIM*INNER) + tid*16;
        const float* xb = x + (size_t)b*DIM*TLEN + t0;
        const char* xp = (const char*)(xb + (size_t)(tid >> 5)*TLEN) + (tid & 31)*16;
        #pragma unroll
        for (int i = 0; i < 8; i++) {
            cp16(s_wsq + i*4096, wq + i*4096);
            cp16(s_wsk + i*4096, wk + i*4096);
            cp16(s_xs  + i*4096, xp + (size_t)(8*i)*TLEN*4);
        }
        CP_COMMIT();
        CP_WAIT(0);
    }
    __syncthreads();

    // xsum: conflict-free — thread (kk = tid>>2, q = tid&3) sums 32 contiguous
    // floats of row kk, with XOR-swizzled chunk order to spread banks.
    {
        int kk = tid >> 2, q = tid & 3;
        const float* xrow = xs + kk*TT + q*32;
        float s = 0.f;
        #pragma unroll
        for (int i = 0; i < 8; i++) {
            int j = (i + kk) & 7;
            float4 v = *(const float4*)&xrow[j*4];
            s += (v.x + v.y) + (v.z + v.w);
        }
        s += __shfl_down_sync(0xffffffffu, s, 2, 4);
        s += __shfl_down_sync(0xffffffffu, s, 1, 4);
        if (q == 0) atomicAdd(&g_xsum[b*DIM + kk], s);
    }

    u64 accQ[8][4], accK[8][4];
    #pragma unroll
    for (int j = 0; j < 8; j++)
        #pragma unroll
        for (int p = 0; p < 4; p++) { accQ[j][p] = 0ull; accK[j][p] = 0ull; }

    // ---- FUSED mainloop: x read once per kk, feeds both Wq and Wk ----
    #pragma unroll 4
    for (int kk = 0; kk < DIM; kk++) {
        ulonglong2 xa = *(const ulonglong2*)&xs[kk*TT + tx*4];
        ulonglong2 xb = *(const ulonglong2*)&xs[kk*TT + 64 + tx*4];
        float4 q0 = *(const float4*)&wsq[kk*INNER + ty*8];
        float4 q1 = *(const float4*)&wsq[kk*INNER + ty*8 + 4];
        float4 k0 = *(const float4*)&wsk[kk*INNER + ty*8];
        float4 k1 = *(const float4*)&wsk[kk*INNER + ty*8 + 4];
        float qf[8] = {q0.x,q0.y,q0.z,q0.w,q1.x,q1.y,q1.z,q1.w};
        float kf[8] = {k0.x,k0.y,k0.z,k0.w,k1.x,k1.y,k1.z,k1.w};
        #pragma unroll
        for (int j = 0; j < 8; j++) {
            u64 qd = pack2(qf[j], qf[j]);
            fma2(accQ[j][0], qd, xa.x);
            fma2(accQ[j][1], qd, xa.y);
            fma2(accQ[j][2], qd, xb.x);
            fma2(accQ[j][3], qd, xb.y);
            u64 kd = pack2(kf[j], kf[j]);
            fma2(accK[j][0], kd, xa.x);
            fma2(accK[j][1], kd, xa.y);
            fma2(accK[j][2], kd, xb.x);
            fma2(accK[j][3], kd, xb.y);
        }
    }

    // ---- Phase A epilogue: exp2(qraw) -> E, qsum ----
    #pragma unroll
    for (int j = 0; j < 8; j++) {
        int c = ty*8 + j;
        float e[8]; float s = 0.f;
        #pragma unroll
        for (int p = 0; p < 4; p++) {
            float2 v = unpack2(accQ[j][p]);
            e[2*p]   = ex2(v.x);
            e[2*p+1] = ex2(v.y);
            s += e[2*p] + e[2*p+1];
        }
        #pragma unroll
        for (int off = 8; off > 0; off >>= 1)
            s += __shfl_down_sync(0xffffffffu, s, off, 16);
        if (tx == 0) atomicAdd(&g_qsum[b*INNER + c], s);
        float* eb0 = &g_E[((size_t)b*INNER + c)*TLEN + t0];
        *(float4*)&eb0[tx*4]      = make_float4(e[0], e[1], e[2], e[3]);
        *(float4*)&eb0[64 + tx*4] = make_float4(e[4], e[5], e[6], e[7]);
    }

    // ---- Phase B epilogue: exp2(kraw) -> per-t head softmax -> ksum ----
    u64 pt2[4] = {0ull, 0ull, 0ull, 0ull};
    #pragma unroll
    for (int j = 0; j < 8; j++)
        #pragma unroll
        for (int p = 0; p < 4; p++) {
            float2 v = unpack2(accK[j][p]);
            u64 e2 = pack2(ex2(v.x), ex2(v.y));
            accK[j][p] = e2;
            pt2[p] = add2(pt2[p], e2);
        }
    // t offsets for p: 0->tx*4, 1->tx*4+2, 2->64+tx*4, 3->64+tx*4+2
    *(u64*)&red[ty*TT + tx*4]          = pt2[0];
    *(u64*)&red[ty*TT + tx*4 + 2]      = pt2[1];
    *(u64*)&red[ty*TT + 64 + tx*4]     = pt2[2];
    *(u64*)&red[ty*TT + 64 + tx*4 + 2] = pt2[3];
    __syncthreads();

    // head sums over d (32 channels = 4 consecutive ty rows) -> 1/hs, then ksum
    const int rb = (ty & ~3)*TT;
    const int toff[4] = {tx*4, tx*4 + 2, 64 + tx*4, 64 + tx*4 + 2};
    u64 inv2[4];
    #pragma unroll
    for (int p = 0; p < 4; p++) {
        int o = rb + toff[p];
        u64 h = add2(add2(*(const u64*)&red[o],
                          *(const u64*)&red[o + TT]),
                     add2(*(const u64*)&red[o + 2*TT],
                          *(const u64*)&red[o + 3*TT]));
        float2 hf = unpack2(h);
        inv2[p] = pack2(rcpa(hf.x), rcpa(hf.y));
    }
    #pragma unroll
    for (int j = 0; j < 8; j++) {
        u64 s2 = 0ull;
        #pragma unroll
        for (int p = 0; p < 4; p++) fma2(s2, accK[j][p], inv2[p]);
        float2 v = unpack2(s2);
        float s = v.x + v.y;
        #pragma unroll
        for (int off = 8; off > 0; off >>= 1)
            s += __shfl_down_sync(0xffffffffu, s, off, 16);
        if (tx == 0) atomicAdd(&g_ksum[b*INNER + ty*8 + j], s);
    }
}

// Pass 2: vsum = Wv @ xsum ; A^T[b][c][o] = w_out[o][c] * ksum*vsum/qsum
__global__ void __launch_bounds__(128) k_scale(const float* __restrict__ wqkv,
                                               const float* __restrict__ wout) {
    int b = blockIdx.x, slab = blockIdx.y;   // slab = 8 o's
    int c = threadIdx.x;                     // 128 threads
    __shared__ float ss[INNER];
    __shared__ float xss[DIM];
    if (c < DIM) xss[c] = g_xsum[b*DIM + c];
    __syncthreads();
    float vs = 0.f;
    const float4* wv4 = (const float4*)(wqkv + (size_t)(2*INNER + c)*DIM);
    #pragma unroll
    for (int kk = 0; kk < DIM/4; kk++) {
        float4 w = wv4[kk];
        vs += w.x*xss[4*kk] + w.y*xss[4*kk+1] + w.z*xss[4*kk+2] + w.w*xss[4*kk+3];
    }
    ss[c] = g_ksum[b*INNER + c] * vs / g_qsum[b*INNER + c];
    __syncthreads();
    for (int idx = c; idx < INNER*8; idx += 128) {
        int cc = idx >> 3, o = slab*8 + (idx & 7);
        g_At[(size_t)b*INNER*64 + cc*64 + o] = wout[o*INNER + cc] * ss[cc];
    }
}

// Pass 3: y[b,o,t] = sum_c A[b,o,c] * E[b,c,t] + b_out[o]
// 256t x 64o tile per block; E streamed in 4 stages of 32c, double-buffered
// via cp.async. Addresses decomposed to base(tid)+immediates to keep regs <128.
__global__ void __launch_bounds__(256, 2) k_out(const float* __restrict__ bout,
                                                float* __restrict__ y) {
    extern __shared__ float sm[];
    float* Es0 = sm;                          // [32][TTO] 32 KB
    float* Es1 = sm + 32*TTO;                 // [32][TTO] 32 KB
    float* As  = sm + 2*32*TTO;               // [128][64] 32 KB (c-major, o inner)
    float* bo  = As + INNER*64;               // [64]
    const int b   = blockIdx.y;
    const int t0  = blockIdx.x * TTO;
    const int tid = threadIdx.x;
    const int tx  = tid & 31;    // t quads at tx*4 and 128+tx*4
    const int ty  = tid >> 5;    // 8 o each -> 64 o

    const float* Ebase = &g_E[(size_t)b*INNER*TLEN + t0];
    const char* psrc = (const char*)Ebase
                     + ((size_t)(tid >> 6)*TLEN + (size_t)(tid & 63)*4)*4;
    const char* asrc = (const char*)&g_At[(size_t)b*INNER*64] + tid*16;
    const uint32_t d0 = smem_u32(Es0) + tid*16;
    const uint32_t d1 = smem_u32(Es1) + tid*16;
    const uint32_t da = smem_u32(As)  + tid*16;

    #pragma unroll
    for (int i = 0; i < 8; i++) {
        cp16(da + i*4096, asrc + i*4096);
        cp16(d0 + i*4096, psrc + (size_t)(4*i)*TLEN*4);
    }
    CP_COMMIT();
    if (tid < 64) bo[tid] = bout[tid];

    u64 acc[8][4];
    #pragma unroll
    for (int j = 0; j < 8; j++)
        #pragma unroll
        for (int p = 0; p < 4; p++) acc[j][p] = 0ull;

    #pragma unroll
    for (int h = 0; h < 4; h++) {
        if (h < 3) {
            const uint32_t dst = ((h+1) & 1) ? d1 : d0;
            #pragma unroll
            for (int i = 0; i < 8; i++)
                cp16(dst + i*4096, psrc + (size_t)((h+1)*32 + 4*i)*TLEN*4);
            CP_COMMIT();
            CP_WAIT(1);
        } else {
            CP_WAIT(0);
        }
        __syncthreads();   // stage h visible (h=0: also covers As/bo)

        const float* Eb = (h & 1) ? Es1 : Es0;
        const float* Ah = As + h*32*64 + ty*8;
        #pragma unroll 4
        for (int cc = 0; cc < 32; cc++) {
            ulonglong2 ea = *(const ulonglong2*)&Eb[cc*TTO + tx*4];
            ulonglong2 eb = *(const ulonglong2*)&Eb[cc*TTO + 128 + tx*4];
            float4 a0 = *(const float4*)&Ah[cc*64];
            float4 a1 = *(const float4*)&Ah[cc*64 + 4];
            float af[8] = {a0.x,a0.y,a0.z,a0.w,a1.x,a1.y,a1.z,a1.w};
            #pragma unroll
            for (int j = 0; j < 8; j++) {
                u64 ad = pack2(af[j], af[j]);
                fma2(acc[j][0], ad, ea.x);
                fma2(acc[j][1], ad, ea.y);
                fma2(acc[j][2], ad, eb.x);
                fma2(acc[j][3], ad, eb.y);
            }
        }
        __syncthreads();   // reads done before refill of this buffer
    }

    #pragma unroll
    for (int j = 0; j < 8; j++) {
        int o = ty*8 + j;
        u64 bb = pack2(bo[o], bo[o]);
        ulonglong2 r0, r1;
        r0.x = add2(acc[j][0], bb); r0.y = add2(acc[j][1], bb);
        r1.x = add2(acc[j][2], bb); r1.y = add2(acc[j][3], bb);
        float* yb = &y[((size_t)b*64 + o)*TLEN + t0];
        *(ulonglong2*)&yb[tx*4]       = r0;
        *(ulonglong2*)&yb[128 + tx*4] = r1;
    }
}

#define SMEM_REDUCE ((2*DIM*INNER + DIM*TT + 16*TT)*4)   /* 106496 */
#define SMEM_OUT    ((2*32*TTO + INNER*64 + 64)*4)       /*  98560 */

extern "C" void kernel_launch(void* const* d_in, const int* in_sizes, int n_in,
                              void* d_out, int out_size) {
    const float* x    = (const float*)d_in[0];
    const float* wqkv = (const float*)d_in[1];
    const float* wout = (const float*)d_in[2];
    const float* bout = (const float*)d_in[3];
    float* y = (float*)d_out;

    cudaFuncSetAttribute((const void*)k_reduce,
                         cudaFuncAttributeMaxDynamicSharedMemorySize, SMEM_REDUCE);
    cudaFuncSetAttribute((const void*)k_out,
                         cudaFuncAttributeMaxDynamicSharedMemorySize, SMEM_OUT);

    k_setup<<<8, 256>>>(wqkv);
    dim3 g(NTILES, BATCH);
    k_reduce<<<g, 256, SMEM_REDUCE>>>(x);
    dim3 gs(BATCH, 8);
    k_scale<<<gs, 128>>>(wqkv, wout);
    dim3 go(NTILES_O, BATCH);
    k_out<<<go, 256, SMEM_OUT>>>(bout, y);
}

// round 16
// speedup vs baseline: 1.1035x; 1.1035x over previous
#include <cuda_runtime.h>
#include <cuda_fp16.h>
#include <cstdint>

typedef unsigned long long u64;

#define BATCH 8
#define DIM   64
#define TLEN  16384
#define INNER 128
#define TT    128
#define NTILES (TLEN/TT)
#define TTO   256
#define NTILES_O (TLEN/TTO)
#define LOG2E 1.4426950408889634f

// Scratch (device globals; no runtime allocation)
__device__ __half g_Eh[(size_t)BATCH*INNER*TLEN]; // 32 MB: exp(qraw) in fp16
__device__ float g_qsum[BATCH*INNER];
__device__ float g_ksum[BATCH*INNER];
__device__ float g_xsum[BATCH*DIM];
__device__ float g_At[BATCH*INNER*64];            // A transposed: [b][c][o]
__device__ float g_W2[2*DIM*INNER];               // [w][kk][c]: transposed, *log2e

// ---- packed fp32x2 helpers (Blackwell) ----
__device__ __forceinline__ u64 pack2(float lo, float hi) {
    u64 r; asm("mov.b64 %0, {%1,%2};" : "=l"(r) : "f"(lo), "f"(hi)); return r;
}
__device__ __forceinline__ float2 unpack2(u64 v) {
    float lo, hi; asm("mov.b64 {%0,%1}, %2;" : "=f"(lo), "=f"(hi) : "l"(v));
    return make_float2(lo, hi);
}
__device__ __forceinline__ void fma2(u64 &d, u64 a, u64 b) {
    asm("fma.rn.f32x2 %0, %1, %2, %0;" : "+l"(d) : "l"(a), "l"(b));
}
__device__ __forceinline__ u64 add2(u64 a, u64 b) {
    u64 r; asm("add.rn.f32x2 %0, %1, %2;" : "=l"(r) : "l"(a), "l"(b)); return r;
}
__device__ __forceinline__ float ex2(float x) {
    float r; asm("ex2.approx.f32 %0, %1;" : "=f"(r) : "f"(x)); return r;
}
__device__ __forceinline__ float rcpa(float x) {
    float r; asm("rcp.approx.f32 %0, %1;" : "=f"(r) : "f"(x)); return r;
}
__device__ __forceinline__ uint32_t smem_u32(const void* p) {
    uint32_t a;
    asm("{ .reg .u64 t; cvta.to.shared.u64 t, %1; cvt.u32.u64 %0, t; }"
        : "=r"(a) : "l"(p));
    return a;
}
__device__ __forceinline__ void cp16(uint32_t dst, const void* src) {
    asm volatile("cp.async.cg.shared.global [%0], [%1], 16;" :: "r"(dst), "l"(src));
}
#define CP_COMMIT() asm volatile("cp.async.commit_group;" ::: "memory")
#define CP_WAIT(N)  asm volatile("cp.async.wait_group %0;" :: "n"(N) : "memory")

// half2 (as u32) -> f32x2 (as u64)
__device__ __forceinline__ u64 h2_to_f2(uint32_t h) {
    __half2 hh = *reinterpret_cast<__half2*>(&h);
    float2 f = __half22float2(hh);
    return pack2(f.x, f.y);
}

// Merged setup: zero accumulators + pre-transform W (transpose + *log2e).
__global__ void k_setup(const float* __restrict__ wqkv) {
    int i = blockIdx.x*blockDim.x + threadIdx.x;
    if (i < BATCH*INNER) { g_qsum[i] = 0.f; g_ksum[i] = 0.f; }
    if (i < BATCH*DIM)   { g_xsum[i] = 0.f; }
    for (int idx = i; idx < 2*DIM*INNER; idx += gridDim.x*blockDim.x) {
        int w = idx >> 13;
        int r = idx & 8191;
        int kk = r >> 7, c = r & 127;
        g_W2[idx] = wqkv[w*INNER*DIM + c*DIM + kk] * LOG2E;
    }
}

// 128(c) x 128(t) tile GEMM; W fp32 in smem, duplicated to f32x2 in regs.
// Thread's 8 t's = {tx*4..+3} and {64+tx*4..+3}  (conflict-free LDS.128).
__device__ __forceinline__ void mm_tile3(const float* __restrict__ xs,
                                         const float* __restrict__ ws,
                                         int tx, int ty, u64 acc[8][4]) {
    #pragma unroll 8
    for (int kk = 0; kk < DIM; kk++) {
        ulonglong2 xa = *(const ulonglong2*)&xs[kk*TT + tx*4];
        ulonglong2 xb = *(const ulonglong2*)&xs[kk*TT + 64 + tx*4];
        float4 w0 = *(const float4*)&ws[kk*INNER + ty*8];
        float4 w1 = *(const float4*)&ws[kk*INNER + ty*8 + 4];
        float wf[8] = {w0.x,w0.y,w0.z,w0.w,w1.x,w1.y,w1.z,w1.w};
        #pragma unroll
        for (int j = 0; j < 8; j++) {
            u64 wd = pack2(wf[j], wf[j]);
            fma2(acc[j][0], wd, xa.x);
            fma2(acc[j][1], wd, xa.y);
            fma2(acc[j][2], wd, xb.x);
            fma2(acc[j][3], wd, xb.y);
        }
    }
}

// Pass 1: per (b, t-tile): qraw -> exp2 -> E(fp16) + qsum ; kraw -> per-t head
// softmax -> ksum ; xsum. W buffers + x filled via one cp.async group.
__global__ void __launch_bounds__(256) k_reduce(const float* __restrict__ x) {
    extern __shared__ float sm[];
    float* wsq = sm;                 // [64][128] 32 KB
    float* wsk = sm + DIM*INNER;     // [64][128] 32 KB
    float* xs  = sm + 2*DIM*INNER;   // [64][TT]  32 KB
    float* red = xs + DIM*TT;        // [16][TT]   8 KB
    const int b   = blockIdx.y;
    const int t0  = blockIdx.x * TT;
    const int tid = threadIdx.x;
    const int tx  = tid & 15;   // t quads at tx*4 and 64+tx*4
    const int ty  = tid >> 4;   // c subtile (8 consecutive c each)

    // ---- async fills: wsq, wsk (straight copies), xs (row-chunked) ----
    {
        const uint32_t s_wsq = smem_u32(wsq) + tid*16;
        const uint32_t s_wsk = smem_u32(wsk) + tid*16;
        const uint32_t s_xs  = smem_u32(xs)  + tid*16;
        const char* wq = (const char*)g_W2 + tid*16;
        const char* wk = (const char*)(g_W2 + DIM*INNER) + tid*16;
        const float* xb = x + (size_t)b*DIM*TLEN + t0;
        const char* xp = (const char*)(xb + (size_t)(tid >> 5)*TLEN) + (tid & 31)*16;
        #pragma unroll
        for (int i = 0; i < 8; i++) {
            cp16(s_wsq + i*4096, wq + i*4096);
            cp16(s_wsk + i*4096, wk + i*4096);
            cp16(s_xs  + i*4096, xp + (size_t)(8*i)*TLEN*4);
        }
        CP_COMMIT();
        CP_WAIT(0);
    }
    __syncthreads();

    // xsum: conflict-free — thread (kk = tid>>2, q = tid&3) sums 32 contiguous
    // floats of row kk, with XOR-swizzled chunk order to spread banks.
    {
        int kk = tid >> 2, q = tid & 3;
        const float* xrow = xs + kk*TT + q*32;
        float s = 0.f;
        #pragma unroll
        for (int i = 0; i < 8; i++) {
            int j = (i + kk) & 7;
            float4 v = *(const float4*)&xrow[j*4];
            s += (v.x + v.y) + (v.z + v.w);
        }
        s += __shfl_down_sync(0xffffffffu, s, 2, 4);
        s += __shfl_down_sync(0xffffffffu, s, 1, 4);
        if (q == 0) atomicAdd(&g_xsum[b*DIM + kk], s);
    }

    u64 acc[8][4];
    #pragma unroll
    for (int j = 0; j < 8; j++)
        #pragma unroll
        for (int p = 0; p < 4; p++) acc[j][p] = 0ull;

    // ---- Phase A: qraw ----
    mm_tile3(xs, wsq, tx, ty, acc);

    #pragma unroll
    for (int j = 0; j < 8; j++) {
        int c = ty*8 + j;
        float e[8]; float s = 0.f;
        #pragma unroll
        for (int p = 0; p < 4; p++) {
            float2 v = unpack2(acc[j][p]);
            e[2*p]   = ex2(v.x);
            e[2*p+1] = ex2(v.y);
            s += e[2*p] + e[2*p+1];
        }
        #pragma unroll
        for (int off = 8; off > 0; off >>= 1)
            s += __shfl_down_sync(0xffffffffu, s, off, 16);
        if (tx == 0) atomicAdd(&g_qsum[b*INNER + c], s);
        // fp16 store: two 8B quads
        __half2 h0 = __floats2half2_rn(e[0], e[1]);
        __half2 h1 = __floats2half2_rn(e[2], e[3]);
        __half2 h2 = __floats2half2_rn(e[4], e[5]);
        __half2 h3 = __floats2half2_rn(e[6], e[7]);
        __half* eb0 = &g_Eh[((size_t)b*INNER + c)*TLEN + t0];
        *(uint2*)&eb0[tx*4]      = make_uint2(*(uint32_t*)&h0, *(uint32_t*)&h1);
        *(uint2*)&eb0[64 + tx*4] = make_uint2(*(uint32_t*)&h2, *(uint32_t*)&h3);
    }

    // ---- Phase B: kraw (wsk already resident; no barrier needed) ----
    #pragma unroll
    for (int j = 0; j < 8; j++)
        #pragma unroll
        for (int p = 0; p < 4; p++) acc[j][p] = 0ull;

    mm_tile3(xs, wsk, tx, ty, acc);

    // exp2 + per-t partial sums (packed over t pairs)
    u64 pt2[4] = {0ull, 0ull, 0ull, 0ull};
    #pragma unroll
    for (int j = 0; j < 8; j++)
        #pragma unroll
        for (int p = 0; p < 4; p++) {
            float2 v = unpack2(acc[j][p]);
            u64 e2 = pack2(ex2(v.x), ex2(v.y));
            acc[j][p] = e2;
            pt2[p] = add2(pt2[p], e2);
        }
    // t offsets for p: 0->tx*4, 1->tx*4+2, 2->64+tx*4, 3->64+tx*4+2
    *(u64*)&red[ty*TT + tx*4]          = pt2[0];
    *(u64*)&red[ty*TT + tx*4 + 2]      = pt2[1];
    *(u64*)&red[ty*TT + 64 + tx*4]     = pt2[2];
    *(u64*)&red[ty*TT + 64 + tx*4 + 2] = pt2[3];
    __syncthreads();

    // head sums over d (32 channels = 4 consecutive ty rows) -> 1/hs, then ksum
    const int rb = (ty & ~3)*TT;
    const int toff[4] = {tx*4, tx*4 + 2, 64 + tx*4, 64 + tx*4 + 2};
    u64 inv2[4];
    #pragma unroll
    for (int p = 0; p < 4; p++) {
        int o = rb + toff[p];
        u64 h = add2(add2(*(const u64*)&red[o],
                          *(const u64*)&red[o + TT]),
                     add2(*(const u64*)&red[o + 2*TT],
                          *(const u64*)&red[o + 3*TT]));
        float2 hf = unpack2(h);
        inv2[p] = pack2(rcpa(hf.x), rcpa(hf.y));
    }
    #pragma unroll
    for (int j = 0; j < 8; j++) {
        u64 s2 = 0ull;
        #pragma unroll
        for (int p = 0; p < 4; p++) fma2(s2, acc[j][p], inv2[p]);
        float2 v = unpack2(s2);
        float s = v.x + v.y;
        #pragma unroll
        for (int off = 8; off > 0; off >>= 1)
            s += __shfl_down_sync(0xffffffffu, s, off, 16);
        if (tx == 0) atomicAdd(&g_ksum[b*INNER + ty*8 + j], s);
    }
}

// Pass 2: vsum = Wv @ xsum ; A^T[b][c][o] = w_out[o][c] * ksum*vsum/qsum
__global__ void __launch_bounds__(128) k_scale(const float* __restrict__ wqkv,
                                               const float* __restrict__ wout) {
    int b = blockIdx.x, slab = blockIdx.y;   // slab = 8 o's
    int c = threadIdx.x;                     // 128 threads
    __shared__ float ss[INNER];
    __shared__ float xss[DIM];
    if (c < DIM) xss[c] = g_xsum[b*DIM + c];
    __syncthreads();
    float vs = 0.f;
    const float4* wv4 = (const float4*)(wqkv + (size_t)(2*INNER + c)*DIM);
    #pragma unroll
    for (int kk = 0; kk < DIM/4; kk++) {
        float4 w = wv4[kk];
        vs += w.x*xss[4*kk] + w.y*xss[4*kk+1] + w.z*xss[4*kk+2] + w.w*xss[4*kk+3];
    }
    ss[c] = g_ksum[b*INNER + c] * vs / g_qsum[b*INNER + c];
    __syncthreads();
    for (int idx = c; idx < INNER*8; idx += 128) {
        int cc = idx >> 3, o = slab*8 + (idx & 7);
        g_At[(size_t)b*INNER*64 + cc*64 + o] = wout[o*INNER + cc] * ss[cc];
    }
}

// Pass 3: y[b,o,t] = sum_c A[b,o,c] * E[b,c,t] + b_out[o]
// 256t x 64o tile per block; E (fp16) streamed in 4 stages of 32c,
// double-buffered via cp.async. Convert half2->f32x2 in regs, fma2 accumulate.
__global__ void __launch_bounds__(256, 2) k_out(const float* __restrict__ bout,
                                                float* __restrict__ y) {
    extern __shared__ float sm[];
    __half* Es0 = (__half*)sm;                 // [32][TTO] half 16 KB
    __half* Es1 = Es0 + 32*TTO;                // [32][TTO] half 16 KB
    float* As   = sm + 2*32*TTO/2;             // [128][64] 32 KB (c-major)
    float* bo   = As + INNER*64;               // [64]
    const int b   = blockIdx.y;
    const int t0  = blockIdx.x * TTO;
    const int tid = threadIdx.x;
    const int tx  = tid & 31;    // t quads at tx*4 and 128+tx*4
    const int ty  = tid >> 5;    // 8 o each -> 64 o

    // E stage = 32c x 256t x 2B = 16KB = 1024 chunks of 16B; 4 per thread.
    // chunk idx = tid + i*256: c = idx>>5 = (tid>>5)+8i, off16 = idx&31.
    const __half* Ebase = &g_Eh[(size_t)b*INNER*TLEN + t0];
    const char* psrc = (const char*)Ebase
                     + (size_t)(tid >> 5)*TLEN*2 + (size_t)(tid & 31)*16;
    const char* asrc = (const char*)&g_At[(size_t)b*INNER*64] + tid*16;
    const uint32_t d0 = smem_u32(Es0) + tid*16;
    const uint32_t d1 = smem_u32(Es1) + tid*16;
    const uint32_t da = smem_u32(As)  + tid*16;

    // group 0: As (32KB, 8 chunks/thread) + E stage 0 (16KB, 4 chunks/thread)
    #pragma unroll
    for (int i = 0; i < 8; i++)
        cp16(da + i*4096, asrc + i*4096);
    #pragma unroll
    for (int i = 0; i < 4; i++)
        cp16(d0 + i*4096, psrc + (size_t)(8*i)*TLEN*2);
    CP_COMMIT();
    if (tid < 64) bo[tid] = bout[tid];

    u64 acc[8][4];
    #pragma unroll
    for (int j = 0; j < 8; j++)
        #pragma unroll
        for (int p = 0; p < 4; p++) acc[j][p] = 0ull;

    #pragma unroll
    for (int h = 0; h < 4; h++) {
        if (h < 3) {
            const uint32_t dst = ((h+1) & 1) ? d1 : d0;
            #pragma unroll
            for (int i = 0; i < 4; i++)
                cp16(dst + i*4096, psrc + (size_t)((h+1)*32 + 8*i)*TLEN*2);
            CP_COMMIT();
            CP_WAIT(1);
        } else {
            CP_WAIT(0);
        }
        __syncthreads();   // stage h visible (h=0: also covers As/bo)

        const __half* Eb = (h & 1) ? Es1 : Es0;
        const float* Ah = As + h*32*64 + ty*8;
        #pragma unroll 4
        for (int cc = 0; cc < 32; cc++) {
            uint2 ha = *(const uint2*)&Eb[cc*TTO + tx*4];
            uint2 hb = *(const uint2*)&Eb[cc*TTO + 128 + tx*4];
            u64 ea0 = h2_to_f2(ha.x), ea1 = h2_to_f2(ha.y);
            u64 eb0 = h2_to_f2(hb.x), eb1 = h2_to_f2(hb.y);
            float4 a0 = *(const float4*)&Ah[cc*64];
            float4 a1 = *(const float4*)&Ah[cc*64 + 4];
            float af[8] = {a0.x,a0.y,a0.z,a0.w,a1.x,a1.y,a1.z,a1.w};
            #pragma unroll
            for (int j = 0; j < 8; j++) {
                u64 ad = pack2(af[j], af[j]);
                fma2(acc[j][0], ad, ea0);
                fma2(acc[j][1], ad, ea1);
                fma2(acc[j][2], ad, eb0);
                fma2(acc[j][3], ad, eb1);
            }
        }
        __syncthreads();   // reads done before refill of this buffer
    }

    #pragma unroll
    for (int j = 0; j < 8; j++) {
        int o = ty*8 + j;
        u64 bb = pack2(bo[o], bo[o]);
        ulonglong2 r0, r1;
        r0.x = add2(acc[j][0], bb); r0.y = add2(acc[j][1], bb);
        r1.x = add2(acc[j][2], bb); r1.y = add2(acc[j][3], bb);
        float* yb = &y[((size_t)b*64 + o)*TLEN + t0];
        *(ulonglong2*)&yb[tx*4]       = r0;
        *(ulonglong2*)&yb[128 + tx*4] = r1;
    }
}

#define SMEM_REDUCE ((2*DIM*INNER + DIM*TT + 16*TT)*4)   /* 106496 */
#define SMEM_OUT    (2*32*TTO*2 + (INNER*64 + 64)*4)     /*  65792 */

extern "C" void kernel_launch(void* const* d_in, const int* in_sizes, int n_in,
                              void* d_out, int out_size) {
    const float* x    = (const float*)d_in[0];
    const float* wqkv = (const float*)d_in[1];
    const float* wout = (const float*)d_in[2];
    const float* bout = (const float*)d_in[3];
    float* y = (float*)d_out;

    cudaFuncSetAttribute((const void*)k_reduce,
                         cudaFuncAttributeMaxDynamicSharedMemorySize, SMEM_REDUCE);
    cudaFuncSetAttribute((const void*)k_out,
                         cudaFuncAttributeMaxDynamicSharedMemorySize, SMEM_OUT);

    k_setup<<<8, 256>>>(wqkv);
    dim3 g(NTILES, BATCH);
    k_reduce<<<g, 256, SMEM_REDUCE>>>(x);
    dim3 gs(BATCH, 8);
    k_scale<<<gs, 128>>>(wqkv, wout);
    dim3 go(NTILES_O, BATCH);
    k_out<<<go, 256, SMEM_OUT>>>(bout, y);
}